// round 14
// baseline (speedup 1.0000x reference)
#include <cuda_runtime.h>
#include <cuda_fp16.h>
#include <cstdint>

#define C_IN    64
#define C_OUT   32
#define M_TILE  128
#define THREADS 256
#define GRID    592
#define N_IN_MAX 100000
#define A_STRIDE_B 144      // bytes per A row: 128 fp16 data + 16 pad (ldmatrix conflict-free)
#define A_TILE_B  (M_TILE * A_STRIDE_B)   // 18432

// dynamic smem layout (byte offsets, 16B aligned)
#define OFF_IN(s)   ((s) * 1024)
#define OFF_OUT(s)  (2048 + (s) * 1024)
#define OFF_MBAR    4096
#define OFF_A(s)    (4352 + (s) * A_TILE_B)
#define SMEM_TOTAL  (4352 + 2 * A_TILE_B)   // 41216

__device__ __align__(16) __half g_featsH[N_IN_MAX * C_IN];   // fp16 feats scratch
__device__ int g_idx_is64;

// Fused prep: (a) index-width detection, (b) feats fp32 -> fp16, (c) zero d_out.
__global__ void __launch_bounds__(256) prep_kernel(const float4* __restrict__ feats, int n4,
                                                   float4* __restrict__ out, int no4,
                                                   const long long* __restrict__ im) {
    int i = blockIdx.x * blockDim.x + threadIdx.x;
    int stride = gridDim.x * blockDim.x;

    if (i == 0) {   // runtime int64-vs-int32 map detection (JAX x32 silently downcasts)
        int is64 = 1;
#pragma unroll
        for (int t = 0; t < 16; ++t) {
            long long v = im[t];
            if (v < 0 || v >= (1ll << 31)) is64 = 0;
        }
        g_idx_is64 = is64;
    }

    uint2* fh = (uint2*)g_featsH;     // one uint2 = 4 fp16 = one float4 source
    for (int j = i; j < n4; j += stride) {
        float4 a = feats[j];
        __half2 a0 = __floats2half2_rn(a.x, a.y), a1 = __floats2half2_rn(a.z, a.w);
        fh[j] = make_uint2(*(uint32_t*)&a0, *(uint32_t*)&a1);
    }

    float4 z = make_float4(0.f, 0.f, 0.f, 0.f);
    for (int j = i; j < no4; j += stride) out[j] = z;
}

static __device__ __forceinline__ uint32_t smem_u32(const void* p) {
    uint32_t a;
    asm("{ .reg .u64 t; cvta.to.shared.u64 t, %1; cvt.u32.u64 %0, t; }" : "=r"(a) : "l"(p));
    return a;
}
static __device__ __forceinline__ void ldm_x4(uint32_t& a0, uint32_t& a1,
                                              uint32_t& a2, uint32_t& a3, uint32_t sa) {
    asm volatile("ldmatrix.sync.aligned.m8n8.x4.shared.b16 {%0,%1,%2,%3}, [%4];"
                 : "=r"(a0), "=r"(a1), "=r"(a2), "=r"(a3) : "r"(sa));
}
static __device__ __forceinline__ void mma_f16(
    float& c0, float& c1, float& c2, float& c3,
    uint32_t a0, uint32_t a1, uint32_t a2, uint32_t a3,
    uint32_t b0, uint32_t b1)
{
    asm volatile(
        "mma.sync.aligned.m16n8k16.row.col.f32.f16.f16.f32 "
        "{%0,%1,%2,%3}, {%4,%5,%6,%7}, {%8,%9}, {%0,%1,%2,%3};"
        : "+f"(c0), "+f"(c1), "+f"(c2), "+f"(c3)
        : "r"(a0), "r"(a1), "r"(a2), "r"(a3), "r"(b0), "r"(b1));
}
static __device__ __forceinline__ void red_v4(float* p, float4 v) {
    asm volatile("red.global.add.v4.f32 [%0], {%1, %2, %3, %4};"
                 :: "l"(p), "f"(v.x), "f"(v.y), "f"(v.z), "f"(v.w) : "memory");
}
static __device__ __forceinline__ uint32_t h2u(__half2 h) {
    return *(uint32_t*)&h;
}
static __device__ __forceinline__ void mbar_init(uint32_t a, uint32_t n) {
    asm volatile("mbarrier.init.shared.b64 [%0], %1;" :: "r"(a), "r"(n) : "memory");
}
static __device__ __forceinline__ void expect_tx(uint32_t a, uint32_t bytes) {
    asm volatile("mbarrier.arrive.expect_tx.shared.b64 _, [%0], %1;"
                 :: "r"(a), "r"(bytes) : "memory");
}
static __device__ __forceinline__ void mbar_wait(uint32_t a, uint32_t ph) {
    asm volatile("{\n\t.reg .pred P1;\n\t"
        "WL_%=:\n\t"
        "mbarrier.try_wait.parity.acquire.cta.shared::cta.b64 P1, [%0], %1, 0x989680;\n\t"
        "@P1 bra.uni WD_%=;\n\t"
        "bra.uni WL_%=;\n\t"
        "WD_%=:\n\t}" :: "r"(a), "r"(ph) : "memory");
}
static __device__ __forceinline__ void bulk_g2s(uint32_t dst, const void* src,
                                                uint32_t bytes, uint32_t mbar) {
    asm volatile(
        "cp.async.bulk.shared::cta.global.mbarrier::complete_tx::bytes [%0], [%1], %2, [%3];"
        :: "r"(dst), "l"(src), "r"(bytes), "r"(mbar) : "memory");
}
#define FENCE_ASYNC() asm volatile("fence.proxy.async.shared::cta;" ::: "memory")

__global__ void __launch_bounds__(THREADS, 4)
spconv_mma(const float* __restrict__ weight,
           const void* __restrict__ in_map, const void* __restrict__ out_map,
           float* __restrict__ out, int M, int tilesPerK, int nTiles, int chunk)
{
    extern __shared__ __align__(16) char smem[];
    const uint32_t sb = smem_u32(smem);

    const int t0 = blockIdx.x * chunk;
    if (t0 >= nTiles) return;
    const int tEnd = min(t0 + chunk, nTiles);

    const int tid  = threadIdx.x;
    const int wid  = tid >> 5;          // 0..7
    const int lane = tid & 31;
    const int grp  = lane >> 2;
    const int tig  = lane & 3;
    const int wbase = wid * 16;         // each warp owns 16 rows of the tile
    const int is64  = g_idx_is64;
    const int idxsz = is64 ? 8 : 4;

    // ldmatrix per-lane source offset within the A tile (fixed per thread)
    const int lr = lane & 7, sel = lane >> 3;
    const uint32_t a_lane_off =
        (uint32_t)((wbase + lr + ((sel & 1) << 3)) * A_STRIDE_B + ((sel >> 1) << 4));

    if (tid == 0) { mbar_init(sb + OFF_MBAR, 1); mbar_init(sb + OFF_MBAR + 8, 1); }
    __syncthreads();

#define MBAR(s) (sb + OFF_MBAR + 8u * (uint32_t)(s))
#define ADV(k, m) do { (m) += M_TILE; if ((m) >= M) { (m) = 0; ++(k); } } while (0)
#define ROWS_AT(m)  min(M_TILE, M - (m))
#define MAPB(k, m)  (((long long)(k) * M + (m)) * idxsz)

    int pk = t0 / tilesPerK;
    int pm = (t0 - pk * tilesPerK) * M_TILE;

    int ph[2] = {0, 0};
    const int cur0 = t0 & 1, nxt0 = cur0 ^ 1;
    const int rows0 = ROWS_AT(pm);

    // ---- prologue stage A: fetch in-idx(t0) ----
    if (tid == 0) {
        expect_tx(MBAR(cur0), (uint32_t)(rows0 * idxsz));
        bulk_g2s(sb + OFF_IN(cur0), (const char*)in_map + MAPB(pk, pm),
                 rows0 * idxsz, MBAR(cur0));
    }
    mbar_wait(MBAR(cur0), 0); ph[cur0] = 1;

    // ---- prologue stage B: gather A(t0) fp16 rows, out-idx(t0), in-idx(t0+1) ----
    {
        int k1 = pk, m1 = pm; ADV(k1, m1);
        int rows1b = (t0 + 1 < tEnd) ? ROWS_AT(m1) : 0;
        uint32_t bytes = (uint32_t)(rows0 * 128 + rows0 * idxsz + rows1b * idxsz);
        if (tid == 0) expect_tx(MBAR(nxt0), bytes);
        if (tid < rows0) {
            long long ii = is64 ? ((const long long*)(smem + OFF_IN(cur0)))[tid]
                                : (long long)((const int*)(smem + OFF_IN(cur0)))[tid];
            bulk_g2s(sb + OFF_A(cur0) + tid * A_STRIDE_B, g_featsH + ii * C_IN, 128, MBAR(nxt0));
        }
        if (tid == 0)
            bulk_g2s(sb + OFF_OUT(cur0), (const char*)out_map + MAPB(pk, pm),
                     rows0 * idxsz, MBAR(nxt0));
        if (tid == 1 && rows1b)
            bulk_g2s(sb + OFF_IN(nxt0), (const char*)in_map + MAPB(k1, m1),
                     rows1b * idxsz, MBAR(nxt0));
    }

    uint32_t B[4][4][2];   // [k-chunk16][n-tile8][2], fp16x2
    int k_cur = -1;

    for (int t = t0; t < tEnd; ++t) {
        const int cur = t & 1, nxt = cur ^ 1;

        mbar_wait(MBAR(nxt), ph[nxt]); ph[nxt] ^= 1;
        __syncthreads();

        const int rows = ROWS_AT(pm);

        if (pk != k_cur) {   // <=2x per CTA (contiguous chunks)
            k_cur = pk;
            const float* Wk = weight + (size_t)pk * C_IN * C_OUT;
#pragma unroll
            for (int kc = 0; kc < 4; ++kc)
#pragma unroll
                for (int nt = 0; nt < 4; ++nt) {
                    const float* Wc = Wk + (kc * 16) * C_OUT + 8 * nt + grp;
                    B[kc][nt][0] = h2u(__floats2half2_rn(Wc[(2 * tig)     * C_OUT],
                                                         Wc[(2 * tig + 1) * C_OUT]));
                    B[kc][nt][1] = h2u(__floats2half2_rn(Wc[(2 * tig + 8) * C_OUT],
                                                         Wc[(2 * tig + 9) * C_OUT]));
                }
        }

        // positions for t+1 and t+2 (cheap incremental advance, no div/mod)
        int k1 = pk, m1 = pm; ADV(k1, m1);
        int k2 = k1, m2 = m1; ADV(k2, m2);

        // ---- issue next tile's async fetches (hidden behind MMA+scatter) ----
        FENCE_ASYNC();
        const int rows1 = (t + 1 < tEnd) ? ROWS_AT(m1) : 0;
        const int rows2 = (t + 2 < tEnd) ? ROWS_AT(m2) : 0;
        uint32_t bytes = (uint32_t)(rows1 * (128 + idxsz) + rows2 * idxsz);
        if (bytes && tid == 0) expect_tx(MBAR(cur), bytes);
        if (rows1) {
            if (tid < rows1) {
                long long ii = is64 ? ((const long long*)(smem + OFF_IN(nxt)))[tid]
                                    : (long long)((const int*)(smem + OFF_IN(nxt)))[tid];
                bulk_g2s(sb + OFF_A(nxt) + tid * A_STRIDE_B, g_featsH + ii * C_IN, 128, MBAR(cur));
            }
            if (tid == 0)
                bulk_g2s(sb + OFF_OUT(nxt), (const char*)out_map + MAPB(k1, m1),
                         rows1 * idxsz, MBAR(cur));
        }
        if (rows2 && tid == 1)
            bulk_g2s(sb + OFF_IN(cur), (const char*)in_map + MAPB(k2, m2),
                     rows2 * idxsz, MBAR(cur));

        // ---- MMA: 16 rows x 32 cols x 64 k per warp = 4 ldmatrix.x4 + 16 HMMA ----
        float acc[4][4];
#pragma unroll
        for (int nt = 0; nt < 4; ++nt)
#pragma unroll
            for (int i = 0; i < 4; ++i) acc[nt][i] = 0.f;

        const uint32_t abase = sb + OFF_A(cur) + a_lane_off;
#pragma unroll
        for (int kc = 0; kc < 4; ++kc) {
            uint32_t a0, a1, a2, a3;
            ldm_x4(a0, a1, a2, a3, abase + kc * 32);
#pragma unroll
            for (int nt = 0; nt < 4; ++nt)
                mma_f16(acc[nt][0], acc[nt][1], acc[nt][2], acc[nt][3],
                        a0, a1, a2, a3, B[kc][nt][0], B[kc][nt][1]);
        }

        // ---- scatter epilogue: shuffle-assembled red.v4 (half the REDG lane-ops) ----
        // Lane pair (tig, tig^1) holds the 4 consecutive cols of rows r0/r1 split 2+2.
        // After a bfly exchange: even lanes emit row r0's float4, odd lanes row r1's.
        {
            const char* osm = smem + OFF_OUT(cur);
            const int r0 = wbase + grp;
            const int odd = tig & 1;
            const int myrow = odd ? r0 + 8 : r0;
            const bool valid = myrow < rows;
            uint32_t oi = 0;
            if (valid) oi = is64 ? (uint32_t)((const long long*)osm)[myrow]
                                 : (uint32_t)((const int*)osm)[myrow];
            float* pbase = out + oi * (uint32_t)C_OUT + ((tig & 2) << 1);
#pragma unroll
            for (int nt = 0; nt < 4; ++nt) {
                // even lanes send their r1 pair, odd lanes send their r0 pair
                float sx = odd ? acc[nt][0] : acc[nt][2];
                float sy = odd ? acc[nt][1] : acc[nt][3];
                float rx = __shfl_xor_sync(0xffffffffu, sx, 1);
                float ry = __shfl_xor_sync(0xffffffffu, sy, 1);
                float4 v = odd ? make_float4(rx, ry, acc[nt][2], acc[nt][3])
                               : make_float4(acc[nt][0], acc[nt][1], rx, ry);
                if (valid) red_v4(pbase + 8 * nt, v);
            }
        }

        // advance to t+1
        pk = k1; pm = m1;
    }
#undef MBAR
#undef ADV
#undef ROWS_AT
#undef MAPB
}

extern "C" void kernel_launch(void* const* d_in, const int* in_sizes, int n_in,
                              void* d_out, int out_size) {
    const float* feats  = (const float*)d_in[0];
    const float* weight = (const float*)d_in[1];
    const void*  in_map  = d_in[2];
    const void*  out_map = d_in[3];

    int K = in_sizes[1] / (C_IN * C_OUT);           // 27
    int M = in_sizes[2] / K;                        // 100000
    int tilesPerK = (M + M_TILE - 1) / M_TILE;      // 782
    int nTiles = K * tilesPerK;                     // 21114
    int chunk = (nTiles + GRID - 1) / GRID;         // 36

    static int attr_done = 0;
    if (!attr_done) {
        cudaFuncSetAttribute(spconv_mma,
                             cudaFuncAttributeMaxDynamicSharedMemorySize, SMEM_TOTAL);
        attr_done = 1;
    }

    prep_kernel<<<1184, 256>>>((const float4*)feats, in_sizes[0] / 4,
                               (float4*)d_out, out_size / 4,
                               (const long long*)in_map);
    spconv_mma<<<GRID, THREADS, SMEM_TOTAL>>>(weight, in_map, out_map,
                                              (float*)d_out, M, tilesPerK, nTiles, chunk);
}

// round 15
// speedup vs baseline: 1.0064x; 1.0064x over previous
#include <cuda_runtime.h>
#include <cuda_fp16.h>
#include <cstdint>

#define C_IN    64
#define C_OUT   32
#define M_TILE  128
#define THREADS 256
#define GRID    592
#define N_IN_MAX 100000
#define A_STRIDE_B 144      // bytes per A row: 128 fp16 data + 16 pad (ldmatrix conflict-free)
#define A_TILE_B  (M_TILE * A_STRIDE_B)   // 18432

// dynamic smem layout (byte offsets, 16B aligned)
#define OFF_IN(s)   ((s) * 1024)
#define OFF_OUT(s)  (2048 + (s) * 1024)
#define OFF_MBAR    4096
#define OFF_A(s)    (4352 + (s) * A_TILE_B)
#define SMEM_TOTAL  (4352 + 2 * A_TILE_B)   // 41216

__device__ __align__(16) __half g_featsH[N_IN_MAX * C_IN];   // fp16 feats scratch
__device__ int g_idx_is64;

// Fused prep: (a) index-width detection, (b) feats fp32 -> fp16, (c) zero d_out.
// 2-way unrolled loops (independent iterations -> MLP>=2), wide grid.
__global__ void __launch_bounds__(256) prep_kernel(const float4* __restrict__ feats, int n4,
                                                   float4* __restrict__ out, int no4,
                                                   const long long* __restrict__ im) {
    int i = blockIdx.x * blockDim.x + threadIdx.x;
    int stride = gridDim.x * blockDim.x;

    if (i == 0) {   // runtime int64-vs-int32 map detection (JAX x32 silently downcasts)
        int is64 = 1;
#pragma unroll
        for (int t = 0; t < 16; ++t) {
            long long v = im[t];
            if (v < 0 || v >= (1ll << 31)) is64 = 0;
        }
        g_idx_is64 = is64;
    }

    uint2* fh = (uint2*)g_featsH;     // one uint2 = 4 fp16 = one float4 source
    for (int j = i; j < n4; j += 2 * stride) {
        int j2 = j + stride;
        float4 a = feats[j];
        float4 b = (j2 < n4) ? feats[j2] : make_float4(0.f, 0.f, 0.f, 0.f);
        __half2 a0 = __floats2half2_rn(a.x, a.y), a1 = __floats2half2_rn(a.z, a.w);
        fh[j] = make_uint2(*(uint32_t*)&a0, *(uint32_t*)&a1);
        if (j2 < n4) {
            __half2 b0 = __floats2half2_rn(b.x, b.y), b1 = __floats2half2_rn(b.z, b.w);
            fh[j2] = make_uint2(*(uint32_t*)&b0, *(uint32_t*)&b1);
        }
    }

    float4 z = make_float4(0.f, 0.f, 0.f, 0.f);
    for (int j = i; j < no4; j += 2 * stride) {
        int j2 = j + stride;
        out[j] = z;
        if (j2 < no4) out[j2] = z;
    }
}

static __device__ __forceinline__ uint32_t smem_u32(const void* p) {
    uint32_t a;
    asm("{ .reg .u64 t; cvta.to.shared.u64 t, %1; cvt.u32.u64 %0, t; }" : "=r"(a) : "l"(p));
    return a;
}
static __device__ __forceinline__ void ldm_x4(uint32_t& a0, uint32_t& a1,
                                              uint32_t& a2, uint32_t& a3, uint32_t sa) {
    asm volatile("ldmatrix.sync.aligned.m8n8.x4.shared.b16 {%0,%1,%2,%3}, [%4];"
                 : "=r"(a0), "=r"(a1), "=r"(a2), "=r"(a3) : "r"(sa));
}
static __device__ __forceinline__ void mma_f16(
    float& c0, float& c1, float& c2, float& c3,
    uint32_t a0, uint32_t a1, uint32_t a2, uint32_t a3,
    uint32_t b0, uint32_t b1)
{
    asm volatile(
        "mma.sync.aligned.m16n8k16.row.col.f32.f16.f16.f32 "
        "{%0,%1,%2,%3}, {%4,%5,%6,%7}, {%8,%9}, {%0,%1,%2,%3};"
        : "+f"(c0), "+f"(c1), "+f"(c2), "+f"(c3)
        : "r"(a0), "r"(a1), "r"(a2), "r"(a3), "r"(b0), "r"(b1));
}
static __device__ __forceinline__ void red_v2(float* p, float x, float y) {
    asm volatile("red.global.add.v2.f32 [%0], {%1, %2};"
                 :: "l"(p), "f"(x), "f"(y) : "memory");
}
static __device__ __forceinline__ uint32_t h2u(__half2 h) {
    return *(uint32_t*)&h;
}
static __device__ __forceinline__ void mbar_init(uint32_t a, uint32_t n) {
    asm volatile("mbarrier.init.shared.b64 [%0], %1;" :: "r"(a), "r"(n) : "memory");
}
static __device__ __forceinline__ void expect_tx(uint32_t a, uint32_t bytes) {
    asm volatile("mbarrier.arrive.expect_tx.shared.b64 _, [%0], %1;"
                 :: "r"(a), "r"(bytes) : "memory");
}
static __device__ __forceinline__ void mbar_wait(uint32_t a, uint32_t ph) {
    asm volatile("{\n\t.reg .pred P1;\n\t"
        "WL_%=:\n\t"
        "mbarrier.try_wait.parity.acquire.cta.shared::cta.b64 P1, [%0], %1, 0x989680;\n\t"
        "@P1 bra.uni WD_%=;\n\t"
        "bra.uni WL_%=;\n\t"
        "WD_%=:\n\t}" :: "r"(a), "r"(ph) : "memory");
}
static __device__ __forceinline__ void bulk_g2s(uint32_t dst, const void* src,
                                                uint32_t bytes, uint32_t mbar) {
    asm volatile(
        "cp.async.bulk.shared::cta.global.mbarrier::complete_tx::bytes [%0], [%1], %2, [%3];"
        :: "r"(dst), "l"(src), "r"(bytes), "r"(mbar) : "memory");
}
#define FENCE_ASYNC() asm volatile("fence.proxy.async.shared::cta;" ::: "memory")

__global__ void __launch_bounds__(THREADS, 4)
spconv_mma(const float* __restrict__ weight,
           const void* __restrict__ in_map, const void* __restrict__ out_map,
           float* __restrict__ out, int M, int tilesPerK, int nTiles, int chunk)
{
    extern __shared__ __align__(16) char smem[];
    const uint32_t sb = smem_u32(smem);

    const int t0 = blockIdx.x * chunk;
    if (t0 >= nTiles) return;
    const int tEnd = min(t0 + chunk, nTiles);

    const int tid  = threadIdx.x;
    const int wid  = tid >> 5;          // 0..7
    const int lane = tid & 31;
    const int grp  = lane >> 2;
    const int tig  = lane & 3;
    const int wbase = wid * 16;         // each warp owns 16 rows of the tile
    const int is64  = g_idx_is64;
    const int idxsz = is64 ? 8 : 4;

    // ldmatrix per-lane source offset within the A tile (fixed per thread)
    const int lr = lane & 7, sel = lane >> 3;
    const uint32_t a_lane_off =
        (uint32_t)((wbase + lr + ((sel & 1) << 3)) * A_STRIDE_B + ((sel >> 1) << 4));

    if (tid == 0) { mbar_init(sb + OFF_MBAR, 1); mbar_init(sb + OFF_MBAR + 8, 1); }
    __syncthreads();

#define MBAR(s) (sb + OFF_MBAR + 8u * (uint32_t)(s))
#define ADV(k, m) do { (m) += M_TILE; if ((m) >= M) { (m) = 0; ++(k); } } while (0)
#define ROWS_AT(m)  min(M_TILE, M - (m))
#define MAPB(k, m)  (((long long)(k) * M + (m)) * idxsz)

    int pk = t0 / tilesPerK;
    int pm = (t0 - pk * tilesPerK) * M_TILE;

    int ph[2] = {0, 0};
    const int cur0 = t0 & 1, nxt0 = cur0 ^ 1;
    const int rows0 = ROWS_AT(pm);

    // ---- prologue stage A: fetch in-idx(t0) ----
    if (tid == 0) {
        expect_tx(MBAR(cur0), (uint32_t)(rows0 * idxsz));
        bulk_g2s(sb + OFF_IN(cur0), (const char*)in_map + MAPB(pk, pm),
                 rows0 * idxsz, MBAR(cur0));
    }
    mbar_wait(MBAR(cur0), 0); ph[cur0] = 1;

    // ---- prologue stage B: gather A(t0) fp16 rows, out-idx(t0), in-idx(t0+1) ----
    {
        int k1 = pk, m1 = pm; ADV(k1, m1);
        int rows1b = (t0 + 1 < tEnd) ? ROWS_AT(m1) : 0;
        uint32_t bytes = (uint32_t)(rows0 * 128 + rows0 * idxsz + rows1b * idxsz);
        if (tid == 0) expect_tx(MBAR(nxt0), bytes);
        if (tid < rows0) {
            long long ii = is64 ? ((const long long*)(smem + OFF_IN(cur0)))[tid]
                                : (long long)((const int*)(smem + OFF_IN(cur0)))[tid];
            bulk_g2s(sb + OFF_A(cur0) + tid * A_STRIDE_B, g_featsH + ii * C_IN, 128, MBAR(nxt0));
        }
        if (tid == 0)
            bulk_g2s(sb + OFF_OUT(cur0), (const char*)out_map + MAPB(pk, pm),
                     rows0 * idxsz, MBAR(nxt0));
        if (tid == 1 && rows1b)
            bulk_g2s(sb + OFF_IN(nxt0), (const char*)in_map + MAPB(k1, m1),
                     rows1b * idxsz, MBAR(nxt0));
    }

    uint32_t B[4][4][2];   // [k-chunk16][n-tile8][2], fp16x2
    int k_cur = -1;

    for (int t = t0; t < tEnd; ++t) {
        const int cur = t & 1, nxt = cur ^ 1;

        mbar_wait(MBAR(nxt), ph[nxt]); ph[nxt] ^= 1;
        __syncthreads();

        const int rows = ROWS_AT(pm);

        if (pk != k_cur) {   // <=2x per CTA (contiguous chunks)
            k_cur = pk;
            const float* Wk = weight + (size_t)pk * C_IN * C_OUT;
#pragma unroll
            for (int kc = 0; kc < 4; ++kc)
#pragma unroll
                for (int nt = 0; nt < 4; ++nt) {
                    const float* Wc = Wk + (kc * 16) * C_OUT + 8 * nt + grp;
                    B[kc][nt][0] = h2u(__floats2half2_rn(Wc[(2 * tig)     * C_OUT],
                                                         Wc[(2 * tig + 1) * C_OUT]));
                    B[kc][nt][1] = h2u(__floats2half2_rn(Wc[(2 * tig + 8) * C_OUT],
                                                         Wc[(2 * tig + 9) * C_OUT]));
                }
        }

        // positions for t+1 and t+2 (cheap incremental advance, no div/mod)
        int k1 = pk, m1 = pm; ADV(k1, m1);
        int k2 = k1, m2 = m1; ADV(k2, m2);

        // ---- issue next tile's async fetches (hidden behind MMA+scatter) ----
        FENCE_ASYNC();
        const int rows1 = (t + 1 < tEnd) ? ROWS_AT(m1) : 0;
        const int rows2 = (t + 2 < tEnd) ? ROWS_AT(m2) : 0;
        uint32_t bytes = (uint32_t)(rows1 * (128 + idxsz) + rows2 * idxsz);
        if (bytes && tid == 0) expect_tx(MBAR(cur), bytes);
        if (rows1) {
            if (tid < rows1) {
                long long ii = is64 ? ((const long long*)(smem + OFF_IN(nxt)))[tid]
                                    : (long long)((const int*)(smem + OFF_IN(nxt)))[tid];
                bulk_g2s(sb + OFF_A(nxt) + tid * A_STRIDE_B, g_featsH + ii * C_IN, 128, MBAR(cur));
            }
            if (tid == 0)
                bulk_g2s(sb + OFF_OUT(nxt), (const char*)out_map + MAPB(k1, m1),
                         rows1 * idxsz, MBAR(cur));
        }
        if (rows2 && tid == 1)
            bulk_g2s(sb + OFF_IN(cur), (const char*)in_map + MAPB(k2, m2),
                     rows2 * idxsz, MBAR(cur));

        // ---- MMA: 16 rows x 32 cols x 64 k per warp = 4 ldmatrix.x4 + 16 HMMA ----
        float acc[4][4];
#pragma unroll
        for (int nt = 0; nt < 4; ++nt)
#pragma unroll
            for (int i = 0; i < 4; ++i) acc[nt][i] = 0.f;

        const uint32_t abase = sb + OFF_A(cur) + a_lane_off;
#pragma unroll
        for (int kc = 0; kc < 4; ++kc) {
            uint32_t a0, a1, a2, a3;
            ldm_x4(a0, a1, a2, a3, abase + kc * 32);
#pragma unroll
            for (int nt = 0; nt < 4; ++nt)
                mma_f16(acc[nt][0], acc[nt][1], acc[nt][2], acc[nt][3],
                        a0, a1, a2, a3, B[kc][nt][0], B[kc][nt][1]);
        }

        // ---- scatter epilogue: direct red.v2 from C-frags (best-measured variant) ----
        {
            const char* osm = smem + OFF_OUT(cur);
            int r0 = wbase + grp;
            int r1 = r0 + 8;
            bool v0 = r0 < rows, v1 = r1 < rows;
            uint32_t o0 = 0, o1 = 0;
            if (v0) o0 = is64 ? (uint32_t)((const long long*)osm)[r0]
                              : (uint32_t)((const int*)osm)[r0];
            if (v1) o1 = is64 ? (uint32_t)((const long long*)osm)[r1]
                              : (uint32_t)((const int*)osm)[r1];
            float* p0 = out + o0 * (uint32_t)C_OUT + 2 * tig;
            float* p1 = out + o1 * (uint32_t)C_OUT + 2 * tig;
#pragma unroll
            for (int nt = 0; nt < 4; ++nt) {
                if (v0) red_v2(p0 + 8 * nt, acc[nt][0], acc[nt][1]);
                if (v1) red_v2(p1 + 8 * nt, acc[nt][2], acc[nt][3]);
            }
        }

        // advance to t+1
        pk = k1; pm = m1;
    }
#undef MBAR
#undef ADV
#undef ROWS_AT
#undef MAPB
}

extern "C" void kernel_launch(void* const* d_in, const int* in_sizes, int n_in,
                              void* d_out, int out_size) {
    const float* feats  = (const float*)d_in[0];
    const float* weight = (const float*)d_in[1];
    const void*  in_map  = d_in[2];
    const void*  out_map = d_in[3];

    int K = in_sizes[1] / (C_IN * C_OUT);           // 27
    int M = in_sizes[2] / K;                        // 100000
    int tilesPerK = (M + M_TILE - 1) / M_TILE;      // 782
    int nTiles = K * tilesPerK;                     // 21114
    int chunk = (nTiles + GRID - 1) / GRID;         // 36

    static int attr_done = 0;
    if (!attr_done) {
        cudaFuncSetAttribute(spconv_mma,
                             cudaFuncAttributeMaxDynamicSharedMemorySize, SMEM_TOTAL);
        attr_done = 1;
    }

    prep_kernel<<<2368, 256>>>((const float4*)feats, in_sizes[0] / 4,
                               (float4*)d_out, out_size / 4,
                               (const long long*)in_map);
    spconv_mma<<<GRID, THREADS, SMEM_TOTAL>>>(weight, in_map, out_map,
                                              (float*)d_out, M, tilesPerK, nTiles, chunk);
}

// round 16
// speedup vs baseline: 1.0762x; 1.0693x over previous
#include <cuda_runtime.h>
#include <cuda_fp16.h>
#include <cstdint>

#define C_IN    64
#define C_OUT   32
#define M_TILE  128
#define THREADS 256
#define GRID    592
#define N_IN_MAX  100000
#define N_OUT_MAX 400000
#define A_STRIDE_B 144      // bytes per A row: 128 fp16 data + 16 pad (ldmatrix conflict-free)
#define A_TILE_B  (M_TILE * A_STRIDE_B)   // 18432

// dynamic smem layout (byte offsets, 16B aligned)
#define OFF_IN(s)   ((s) * 1024)
#define OFF_OUT(s)  (2048 + (s) * 1024)
#define OFF_MBAR    4096
#define OFF_A(s)    (4352 + (s) * A_TILE_B)
#define SMEM_TOTAL  (4352 + 2 * A_TILE_B)   // 41216

__device__ __align__(16) __half g_featsH[N_IN_MAX * C_IN];    // fp16 feats scratch
__device__ __align__(16) __half g_outH[N_OUT_MAX * C_OUT];    // fp16 output accumulator
__device__ int g_idx_is64;

// Fused prep: (a) index-width detection, (b) feats fp32 -> fp16, (c) zero fp16 out-accum.
__global__ void __launch_bounds__(256) prep_kernel(const float4* __restrict__ feats, int n4,
                                                   int noh4,
                                                   const long long* __restrict__ im) {
    int i = blockIdx.x * blockDim.x + threadIdx.x;
    int stride = gridDim.x * blockDim.x;

    if (i == 0) {   // runtime int64-vs-int32 map detection (JAX x32 silently downcasts)
        int is64 = 1;
#pragma unroll
        for (int t = 0; t < 16; ++t) {
            long long v = im[t];
            if (v < 0 || v >= (1ll << 31)) is64 = 0;
        }
        g_idx_is64 = is64;
    }

    uint2* fh = (uint2*)g_featsH;     // one uint2 = 4 fp16 = one float4 source
    for (int j = i; j < n4; j += 2 * stride) {
        int j2 = j + stride;
        float4 a = feats[j];
        float4 b = (j2 < n4) ? feats[j2] : make_float4(0.f, 0.f, 0.f, 0.f);
        __half2 a0 = __floats2half2_rn(a.x, a.y), a1 = __floats2half2_rn(a.z, a.w);
        fh[j] = make_uint2(*(uint32_t*)&a0, *(uint32_t*)&a1);
        if (j2 < n4) {
            __half2 b0 = __floats2half2_rn(b.x, b.y), b1 = __floats2half2_rn(b.z, b.w);
            fh[j2] = make_uint2(*(uint32_t*)&b0, *(uint32_t*)&b1);
        }
    }

    uint4* oz = (uint4*)g_outH;       // zero the fp16 accumulator (25.6 MB)
    uint4 z = make_uint4(0u, 0u, 0u, 0u);
    for (int j = i; j < noh4; j += 2 * stride) {
        int j2 = j + stride;
        oz[j] = z;
        if (j2 < noh4) oz[j2] = z;
    }
}

// Final pass: fp16 accumulator -> fp32 d_out (writes every element; no d_out zeroing needed)
__global__ void __launch_bounds__(256) convert_out(float4* __restrict__ out, int no4) {
    int i = blockIdx.x * blockDim.x + threadIdx.x;
    int stride = gridDim.x * blockDim.x;
    const uint2* src = (const uint2*)g_outH;     // uint2 = 4 fp16 -> one float4
    for (int j = i; j < no4; j += 2 * stride) {
        int j2 = j + stride;
        uint2 a = src[j];
        uint2 b = (j2 < no4) ? src[j2] : make_uint2(0u, 0u);
        float2 f0 = __half22float2(*(__half2*)&a.x);
        float2 f1 = __half22float2(*(__half2*)&a.y);
        out[j] = make_float4(f0.x, f0.y, f1.x, f1.y);
        if (j2 < no4) {
            float2 g0 = __half22float2(*(__half2*)&b.x);
            float2 g1 = __half22float2(*(__half2*)&b.y);
            out[j2] = make_float4(g0.x, g0.y, g1.x, g1.y);
        }
    }
}

static __device__ __forceinline__ uint32_t smem_u32(const void* p) {
    uint32_t a;
    asm("{ .reg .u64 t; cvta.to.shared.u64 t, %1; cvt.u32.u64 %0, t; }" : "=r"(a) : "l"(p));
    return a;
}
static __device__ __forceinline__ void ldm_x4(uint32_t& a0, uint32_t& a1,
                                              uint32_t& a2, uint32_t& a3, uint32_t sa) {
    asm volatile("ldmatrix.sync.aligned.m8n8.x4.shared.b16 {%0,%1,%2,%3}, [%4];"
                 : "=r"(a0), "=r"(a1), "=r"(a2), "=r"(a3) : "r"(sa));
}
static __device__ __forceinline__ void mma_f16(
    float& c0, float& c1, float& c2, float& c3,
    uint32_t a0, uint32_t a1, uint32_t a2, uint32_t a3,
    uint32_t b0, uint32_t b1)
{
    asm volatile(
        "mma.sync.aligned.m16n8k16.row.col.f32.f16.f16.f32 "
        "{%0,%1,%2,%3}, {%4,%5,%6,%7}, {%8,%9}, {%0,%1,%2,%3};"
        : "+f"(c0), "+f"(c1), "+f"(c2), "+f"(c3)
        : "r"(a0), "r"(a1), "r"(a2), "r"(a3), "r"(b0), "r"(b1));
}
static __device__ __forceinline__ void red_h2(__half* p, __half2 v) {
    asm volatile("red.global.add.noftz.f16x2 [%0], %1;"
                 :: "l"(p), "r"(*(uint32_t*)&v) : "memory");
}
static __device__ __forceinline__ uint32_t h2u(__half2 h) {
    return *(uint32_t*)&h;
}
static __device__ __forceinline__ void mbar_init(uint32_t a, uint32_t n) {
    asm volatile("mbarrier.init.shared.b64 [%0], %1;" :: "r"(a), "r"(n) : "memory");
}
static __device__ __forceinline__ void expect_tx(uint32_t a, uint32_t bytes) {
    asm volatile("mbarrier.arrive.expect_tx.shared.b64 _, [%0], %1;"
                 :: "r"(a), "r"(bytes) : "memory");
}
static __device__ __forceinline__ void mbar_wait(uint32_t a, uint32_t ph) {
    asm volatile("{\n\t.reg .pred P1;\n\t"
        "WL_%=:\n\t"
        "mbarrier.try_wait.parity.acquire.cta.shared::cta.b64 P1, [%0], %1, 0x989680;\n\t"
        "@P1 bra.uni WD_%=;\n\t"
        "bra.uni WL_%=;\n\t"
        "WD_%=:\n\t}" :: "r"(a), "r"(ph) : "memory");
}
static __device__ __forceinline__ void bulk_g2s(uint32_t dst, const void* src,
                                                uint32_t bytes, uint32_t mbar) {
    asm volatile(
        "cp.async.bulk.shared::cta.global.mbarrier::complete_tx::bytes [%0], [%1], %2, [%3];"
        :: "r"(dst), "l"(src), "r"(bytes), "r"(mbar) : "memory");
}
#define FENCE_ASYNC() asm volatile("fence.proxy.async.shared::cta;" ::: "memory")

__global__ void __launch_bounds__(THREADS, 4)
spconv_mma(const float* __restrict__ weight,
           const void* __restrict__ in_map, const void* __restrict__ out_map,
           int M, int tilesPerK, int nTiles, int chunk)
{
    extern __shared__ __align__(16) char smem[];
    const uint32_t sb = smem_u32(smem);

    const int t0 = blockIdx.x * chunk;
    if (t0 >= nTiles) return;
    const int tEnd = min(t0 + chunk, nTiles);

    const int tid  = threadIdx.x;
    const int wid  = tid >> 5;          // 0..7
    const int lane = tid & 31;
    const int grp  = lane >> 2;
    const int tig  = lane & 3;
    const int wbase = wid * 16;         // each warp owns 16 rows of the tile
    const int is64  = g_idx_is64;
    const int idxsz = is64 ? 8 : 4;
    __half* const outH = g_outH;

    // ldmatrix per-lane source offset within the A tile (fixed per thread)
    const int lr = lane & 7, sel = lane >> 3;
    const uint32_t a_lane_off =
        (uint32_t)((wbase + lr + ((sel & 1) << 3)) * A_STRIDE_B + ((sel >> 1) << 4));

    if (tid == 0) { mbar_init(sb + OFF_MBAR, 1); mbar_init(sb + OFF_MBAR + 8, 1); }
    __syncthreads();

#define MBAR(s) (sb + OFF_MBAR + 8u * (uint32_t)(s))
#define ADV(k, m) do { (m) += M_TILE; if ((m) >= M) { (m) = 0; ++(k); } } while (0)
#define ROWS_AT(m)  min(M_TILE, M - (m))
#define MAPB(k, m)  (((long long)(k) * M + (m)) * idxsz)

    int pk = t0 / tilesPerK;
    int pm = (t0 - pk * tilesPerK) * M_TILE;

    int ph[2] = {0, 0};
    const int cur0 = t0 & 1, nxt0 = cur0 ^ 1;
    const int rows0 = ROWS_AT(pm);

    // ---- prologue stage A: fetch in-idx(t0) ----
    if (tid == 0) {
        expect_tx(MBAR(cur0), (uint32_t)(rows0 * idxsz));
        bulk_g2s(sb + OFF_IN(cur0), (const char*)in_map + MAPB(pk, pm),
                 rows0 * idxsz, MBAR(cur0));
    }
    mbar_wait(MBAR(cur0), 0); ph[cur0] = 1;

    // ---- prologue stage B: gather A(t0) fp16 rows, out-idx(t0), in-idx(t0+1) ----
    {
        int k1 = pk, m1 = pm; ADV(k1, m1);
        int rows1b = (t0 + 1 < tEnd) ? ROWS_AT(m1) : 0;
        uint32_t bytes = (uint32_t)(rows0 * 128 + rows0 * idxsz + rows1b * idxsz);
        if (tid == 0) expect_tx(MBAR(nxt0), bytes);
        if (tid < rows0) {
            long long ii = is64 ? ((const long long*)(smem + OFF_IN(cur0)))[tid]
                                : (long long)((const int*)(smem + OFF_IN(cur0)))[tid];
            bulk_g2s(sb + OFF_A(cur0) + tid * A_STRIDE_B, g_featsH + ii * C_IN, 128, MBAR(nxt0));
        }
        if (tid == 0)
            bulk_g2s(sb + OFF_OUT(cur0), (const char*)out_map + MAPB(pk, pm),
                     rows0 * idxsz, MBAR(nxt0));
        if (tid == 1 && rows1b)
            bulk_g2s(sb + OFF_IN(nxt0), (const char*)in_map + MAPB(k1, m1),
                     rows1b * idxsz, MBAR(nxt0));
    }

    uint32_t B[4][4][2];   // [k-chunk16][n-tile8][2], fp16x2
    int k_cur = -1;

    for (int t = t0; t < tEnd; ++t) {
        const int cur = t & 1, nxt = cur ^ 1;

        mbar_wait(MBAR(nxt), ph[nxt]); ph[nxt] ^= 1;
        __syncthreads();

        const int rows = ROWS_AT(pm);

        if (pk != k_cur) {   // <=2x per CTA (contiguous chunks)
            k_cur = pk;
            const float* Wk = weight + (size_t)pk * C_IN * C_OUT;
#pragma unroll
            for (int kc = 0; kc < 4; ++kc)
#pragma unroll
                for (int nt = 0; nt < 4; ++nt) {
                    const float* Wc = Wk + (kc * 16) * C_OUT + 8 * nt + grp;
                    B[kc][nt][0] = h2u(__floats2half2_rn(Wc[(2 * tig)     * C_OUT],
                                                         Wc[(2 * tig + 1) * C_OUT]));
                    B[kc][nt][1] = h2u(__floats2half2_rn(Wc[(2 * tig + 8) * C_OUT],
                                                         Wc[(2 * tig + 9) * C_OUT]));
                }
        }

        // positions for t+1 and t+2 (cheap incremental advance, no div/mod)
        int k1 = pk, m1 = pm; ADV(k1, m1);
        int k2 = k1, m2 = m1; ADV(k2, m2);

        // ---- issue next tile's async fetches (hidden behind MMA+scatter) ----
        FENCE_ASYNC();
        const int rows1 = (t + 1 < tEnd) ? ROWS_AT(m1) : 0;
        const int rows2 = (t + 2 < tEnd) ? ROWS_AT(m2) : 0;
        uint32_t bytes = (uint32_t)(rows1 * (128 + idxsz) + rows2 * idxsz);
        if (bytes && tid == 0) expect_tx(MBAR(cur), bytes);
        if (rows1) {
            if (tid < rows1) {
                long long ii = is64 ? ((const long long*)(smem + OFF_IN(nxt)))[tid]
                                    : (long long)((const int*)(smem + OFF_IN(nxt)))[tid];
                bulk_g2s(sb + OFF_A(nxt) + tid * A_STRIDE_B, g_featsH + ii * C_IN, 128, MBAR(cur));
            }
            if (tid == 0)
                bulk_g2s(sb + OFF_OUT(nxt), (const char*)out_map + MAPB(k1, m1),
                         rows1 * idxsz, MBAR(cur));
        }
        if (rows2 && tid == 1)
            bulk_g2s(sb + OFF_IN(cur), (const char*)in_map + MAPB(k2, m2),
                     rows2 * idxsz, MBAR(cur));

        // ---- MMA: 16 rows x 32 cols x 64 k per warp = 4 ldmatrix.x4 + 16 HMMA ----
        float acc[4][4];
#pragma unroll
        for (int nt = 0; nt < 4; ++nt)
#pragma unroll
            for (int i = 0; i < 4; ++i) acc[nt][i] = 0.f;

        const uint32_t abase = sb + OFF_A(cur) + a_lane_off;
#pragma unroll
        for (int kc = 0; kc < 4; ++kc) {
            uint32_t a0, a1, a2, a3;
            ldm_x4(a0, a1, a2, a3, abase + kc * 32);
#pragma unroll
            for (int nt = 0; nt < 4; ++nt)
                mma_f16(acc[nt][0], acc[nt][1], acc[nt][2], acc[nt][3],
                        a0, a1, a2, a3, B[kc][nt][0], B[kc][nt][1]);
        }

        // ---- scatter epilogue: fp16x2 reductions (half the scatter bytes/sectors) ----
        {
            const char* osm = smem + OFF_OUT(cur);
            int r0 = wbase + grp;
            int r1 = r0 + 8;
            bool v0 = r0 < rows, v1 = r1 < rows;
            uint32_t o0 = 0, o1 = 0;
            if (v0) o0 = is64 ? (uint32_t)((const long long*)osm)[r0]
                              : (uint32_t)((const int*)osm)[r0];
            if (v1) o1 = is64 ? (uint32_t)((const long long*)osm)[r1]
                              : (uint32_t)((const int*)osm)[r1];
            __half* p0 = outH + o0 * (uint32_t)C_OUT + 2 * tig;
            __half* p1 = outH + o1 * (uint32_t)C_OUT + 2 * tig;
#pragma unroll
            for (int nt = 0; nt < 4; ++nt) {
                if (v0) red_h2(p0 + 8 * nt, __floats2half2_rn(acc[nt][0], acc[nt][1]));
                if (v1) red_h2(p1 + 8 * nt, __floats2half2_rn(acc[nt][2], acc[nt][3]));
            }
        }

        // advance to t+1
        pk = k1; pm = m1;
    }
#undef MBAR
#undef ADV
#undef ROWS_AT
#undef MAPB
}

extern "C" void kernel_launch(void* const* d_in, const int* in_sizes, int n_in,
                              void* d_out, int out_size) {
    const float* feats  = (const float*)d_in[0];
    const float* weight = (const float*)d_in[1];
    const void*  in_map  = d_in[2];
    const void*  out_map = d_in[3];

    int K = in_sizes[1] / (C_IN * C_OUT);           // 27
    int M = in_sizes[2] / K;                        // 100000
    int tilesPerK = (M + M_TILE - 1) / M_TILE;      // 782
    int nTiles = K * tilesPerK;                     // 21114
    int chunk = (nTiles + GRID - 1) / GRID;         // 36

    static int attr_done = 0;
    if (!attr_done) {
        cudaFuncSetAttribute(spconv_mma,
                             cudaFuncAttributeMaxDynamicSharedMemorySize, SMEM_TOTAL);
        attr_done = 1;
    }

    prep_kernel<<<2368, 256>>>((const float4*)feats, in_sizes[0] / 4,
                               out_size / 8,          // fp16 accum as uint4 count
                               (const long long*)in_map);
    spconv_mma<<<GRID, THREADS, SMEM_TOTAL>>>(weight, in_map, out_map,
                                              M, tilesPerK, nTiles, chunk);
    convert_out<<<2368, 256>>>((float4*)d_out, out_size / 4);
}

// round 17
// speedup vs baseline: 1.0868x; 1.0099x over previous
#include <cuda_runtime.h>
#include <cuda_fp16.h>
#include <cstdint>

#define C_IN    64
#define C_OUT   32
#define M_TILE  128
#define THREADS 256
#define GRID    592
#define N_IN_MAX  100000
#define N_OUT_MAX 400000
#define A_STRIDE_B 144      // bytes per A row: 128 fp16 data + 16 pad (ldmatrix conflict-free)
#define A_TILE_B  (M_TILE * A_STRIDE_B)   // 18432

// dynamic smem layout (byte offsets, 16B aligned)
#define OFF_IN(s)   ((s) * 1024)
#define OFF_OUT(s)  (2048 + (s) * 1024)
#define OFF_MBAR    4096
#define OFF_A(s)    (4352 + (s) * A_TILE_B)
#define SMEM_TOTAL  (4352 + 2 * A_TILE_B)   // 41216

__device__ __align__(16) __half g_featsH[N_IN_MAX * C_IN];    // fp16 feats scratch
__device__ __align__(16) __half g_outH[N_OUT_MAX * C_OUT];    // fp16 output accumulator
__device__ int g_idx_is64;

// Fused prep: (a) index-width detection, (b) feats fp32 -> fp16, (c) zero fp16 out-accum.
// 4-way unrolled (independent iterations -> MLP>=4).
__global__ void __launch_bounds__(256) prep_kernel(const float4* __restrict__ feats, int n4,
                                                   int noh4,
                                                   const long long* __restrict__ im) {
    int i = blockIdx.x * blockDim.x + threadIdx.x;
    int stride = gridDim.x * blockDim.x;

    if (i == 0) {   // runtime int64-vs-int32 map detection (JAX x32 silently downcasts)
        int is64 = 1;
#pragma unroll
        for (int t = 0; t < 16; ++t) {
            long long v = im[t];
            if (v < 0 || v >= (1ll << 31)) is64 = 0;
        }
        g_idx_is64 = is64;
    }

    uint2* fh = (uint2*)g_featsH;     // one uint2 = 4 fp16 = one float4 source
    for (int j = i; j < n4; j += 4 * stride) {
#pragma unroll
        for (int u = 0; u < 4; ++u) {
            int jj = j + u * stride;
            if (jj < n4) {
                float4 a = feats[jj];
                __half2 a0 = __floats2half2_rn(a.x, a.y), a1 = __floats2half2_rn(a.z, a.w);
                fh[jj] = make_uint2(*(uint32_t*)&a0, *(uint32_t*)&a1);
            }
        }
    }

    uint4* oz = (uint4*)g_outH;       // zero the fp16 accumulator (25.6 MB)
    uint4 z = make_uint4(0u, 0u, 0u, 0u);
    for (int j = i; j < noh4; j += 4 * stride) {
#pragma unroll
        for (int u = 0; u < 4; ++u) {
            int jj = j + u * stride;
            if (jj < noh4) oz[jj] = z;
        }
    }
}

// Final pass: fp16 accumulator -> fp32 d_out (writes every element; no d_out zeroing needed)
__global__ void __launch_bounds__(256) convert_out(float4* __restrict__ out, int no4) {
    int i = blockIdx.x * blockDim.x + threadIdx.x;
    int stride = gridDim.x * blockDim.x;
    const uint2* src = (const uint2*)g_outH;     // uint2 = 4 fp16 -> one float4
    for (int j = i; j < no4; j += 4 * stride) {
#pragma unroll
        for (int u = 0; u < 4; ++u) {
            int jj = j + u * stride;
            if (jj < no4) {
                uint2 a = src[jj];
                float2 f0 = __half22float2(*(__half2*)&a.x);
                float2 f1 = __half22float2(*(__half2*)&a.y);
                out[jj] = make_float4(f0.x, f0.y, f1.x, f1.y);
            }
        }
    }
}

static __device__ __forceinline__ uint32_t smem_u32(const void* p) {
    uint32_t a;
    asm("{ .reg .u64 t; cvta.to.shared.u64 t, %1; cvt.u32.u64 %0, t; }" : "=r"(a) : "l"(p));
    return a;
}
static __device__ __forceinline__ void ldm_x4(uint32_t& a0, uint32_t& a1,
                                              uint32_t& a2, uint32_t& a3, uint32_t sa) {
    asm volatile("ldmatrix.sync.aligned.m8n8.x4.shared.b16 {%0,%1,%2,%3}, [%4];"
                 : "=r"(a0), "=r"(a1), "=r"(a2), "=r"(a3) : "r"(sa));
}
static __device__ __forceinline__ void mma_f16(
    float& c0, float& c1, float& c2, float& c3,
    uint32_t a0, uint32_t a1, uint32_t a2, uint32_t a3,
    uint32_t b0, uint32_t b1)
{
    asm volatile(
        "mma.sync.aligned.m16n8k16.row.col.f32.f16.f16.f32 "
        "{%0,%1,%2,%3}, {%4,%5,%6,%7}, {%8,%9}, {%0,%1,%2,%3};"
        : "+f"(c0), "+f"(c1), "+f"(c2), "+f"(c3)
        : "r"(a0), "r"(a1), "r"(a2), "r"(a3), "r"(b0), "r"(b1));
}
// vector fp16x2 reduction: 4 consecutive fp16 (8 bytes) in one instruction
static __device__ __forceinline__ void red_h2v2(__half* p, uint32_t u0, uint32_t u1) {
    asm volatile("red.global.add.noftz.v2.f16x2 [%0], {%1, %2};"
                 :: "l"(p), "r"(u0), "r"(u1) : "memory");
}
static __device__ __forceinline__ uint32_t h2u(__half2 h) {
    return *(uint32_t*)&h;
}
static __device__ __forceinline__ void mbar_init(uint32_t a, uint32_t n) {
    asm volatile("mbarrier.init.shared.b64 [%0], %1;" :: "r"(a), "r"(n) : "memory");
}
static __device__ __forceinline__ void expect_tx(uint32_t a, uint32_t bytes) {
    asm volatile("mbarrier.arrive.expect_tx.shared.b64 _, [%0], %1;"
                 :: "r"(a), "r"(bytes) : "memory");
}
static __device__ __forceinline__ void mbar_wait(uint32_t a, uint32_t ph) {
    asm volatile("{\n\t.reg .pred P1;\n\t"
        "WL_%=:\n\t"
        "mbarrier.try_wait.parity.acquire.cta.shared::cta.b64 P1, [%0], %1, 0x989680;\n\t"
        "@P1 bra.uni WD_%=;\n\t"
        "bra.uni WL_%=;\n\t"
        "WD_%=:\n\t}" :: "r"(a), "r"(ph) : "memory");
}
static __device__ __forceinline__ void bulk_g2s(uint32_t dst, const void* src,
                                                uint32_t bytes, uint32_t mbar) {
    asm volatile(
        "cp.async.bulk.shared::cta.global.mbarrier::complete_tx::bytes [%0], [%1], %2, [%3];"
        :: "r"(dst), "l"(src), "r"(bytes), "r"(mbar) : "memory");
}
#define FENCE_ASYNC() asm volatile("fence.proxy.async.shared::cta;" ::: "memory")

__global__ void __launch_bounds__(THREADS, 4)
spconv_mma(const float* __restrict__ weight,
           const void* __restrict__ in_map, const void* __restrict__ out_map,
           int M, int tilesPerK, int nTiles, int chunk)
{
    extern __shared__ __align__(16) char smem[];
    const uint32_t sb = smem_u32(smem);

    const int t0 = blockIdx.x * chunk;
    if (t0 >= nTiles) return;
    const int tEnd = min(t0 + chunk, nTiles);

    const int tid  = threadIdx.x;
    const int wid  = tid >> 5;          // 0..7
    const int lane = tid & 31;
    const int grp  = lane >> 2;
    const int tig  = lane & 3;
    const int wbase = wid * 16;         // each warp owns 16 rows of the tile
    const int is64  = g_idx_is64;
    const int idxsz = is64 ? 8 : 4;
    __half* const outH = g_outH;

    // ldmatrix per-lane source offset within the A tile (fixed per thread)
    const int lr = lane & 7, sel = lane >> 3;
    const uint32_t a_lane_off =
        (uint32_t)((wbase + lr + ((sel & 1) << 3)) * A_STRIDE_B + ((sel >> 1) << 4));

    if (tid == 0) { mbar_init(sb + OFF_MBAR, 1); mbar_init(sb + OFF_MBAR + 8, 1); }
    __syncthreads();

#define MBAR(s) (sb + OFF_MBAR + 8u * (uint32_t)(s))
#define ADV(k, m) do { (m) += M_TILE; if ((m) >= M) { (m) = 0; ++(k); } } while (0)
#define ROWS_AT(m)  min(M_TILE, M - (m))
#define MAPB(k, m)  (((long long)(k) * M + (m)) * idxsz)

    int pk = t0 / tilesPerK;
    int pm = (t0 - pk * tilesPerK) * M_TILE;

    int ph[2] = {0, 0};
    const int cur0 = t0 & 1, nxt0 = cur0 ^ 1;
    const int rows0 = ROWS_AT(pm);

    // ---- prologue stage A: fetch in-idx(t0) ----
    if (tid == 0) {
        expect_tx(MBAR(cur0), (uint32_t)(rows0 * idxsz));
        bulk_g2s(sb + OFF_IN(cur0), (const char*)in_map + MAPB(pk, pm),
                 rows0 * idxsz, MBAR(cur0));
    }
    mbar_wait(MBAR(cur0), 0); ph[cur0] = 1;

    // ---- prologue stage B: gather A(t0) fp16 rows, out-idx(t0), in-idx(t0+1) ----
    {
        int k1 = pk, m1 = pm; ADV(k1, m1);
        int rows1b = (t0 + 1 < tEnd) ? ROWS_AT(m1) : 0;
        uint32_t bytes = (uint32_t)(rows0 * 128 + rows0 * idxsz + rows1b * idxsz);
        if (tid == 0) expect_tx(MBAR(nxt0), bytes);
        if (tid < rows0) {
            long long ii = is64 ? ((const long long*)(smem + OFF_IN(cur0)))[tid]
                                : (long long)((const int*)(smem + OFF_IN(cur0)))[tid];
            bulk_g2s(sb + OFF_A(cur0) + tid * A_STRIDE_B, g_featsH + ii * C_IN, 128, MBAR(nxt0));
        }
        if (tid == 0)
            bulk_g2s(sb + OFF_OUT(cur0), (const char*)out_map + MAPB(pk, pm),
                     rows0 * idxsz, MBAR(nxt0));
        if (tid == 1 && rows1b)
            bulk_g2s(sb + OFF_IN(nxt0), (const char*)in_map + MAPB(k1, m1),
                     rows1b * idxsz, MBAR(nxt0));
    }

    uint32_t B[4][4][2];   // [k-chunk16][n-tile8][2], fp16x2
    int k_cur = -1;

    for (int t = t0; t < tEnd; ++t) {
        const int cur = t & 1, nxt = cur ^ 1;

        mbar_wait(MBAR(nxt), ph[nxt]); ph[nxt] ^= 1;
        __syncthreads();

        const int rows = ROWS_AT(pm);

        if (pk != k_cur) {   // <=2x per CTA (contiguous chunks)
            k_cur = pk;
            const float* Wk = weight + (size_t)pk * C_IN * C_OUT;
#pragma unroll
            for (int kc = 0; kc < 4; ++kc)
#pragma unroll
                for (int nt = 0; nt < 4; ++nt) {
                    const float* Wc = Wk + (kc * 16) * C_OUT + 8 * nt + grp;
                    B[kc][nt][0] = h2u(__floats2half2_rn(Wc[(2 * tig)     * C_OUT],
                                                         Wc[(2 * tig + 1) * C_OUT]));
                    B[kc][nt][1] = h2u(__floats2half2_rn(Wc[(2 * tig + 8) * C_OUT],
                                                         Wc[(2 * tig + 9) * C_OUT]));
                }
        }

        // positions for t+1 and t+2 (cheap incremental advance, no div/mod)
        int k1 = pk, m1 = pm; ADV(k1, m1);
        int k2 = k1, m2 = m1; ADV(k2, m2);

        // ---- issue next tile's async fetches (hidden behind MMA+scatter) ----
        FENCE_ASYNC();
        const int rows1 = (t + 1 < tEnd) ? ROWS_AT(m1) : 0;
        const int rows2 = (t + 2 < tEnd) ? ROWS_AT(m2) : 0;
        uint32_t bytes = (uint32_t)(rows1 * (128 + idxsz) + rows2 * idxsz);
        if (bytes && tid == 0) expect_tx(MBAR(cur), bytes);
        if (rows1) {
            if (tid < rows1) {
                long long ii = is64 ? ((const long long*)(smem + OFF_IN(nxt)))[tid]
                                    : (long long)((const int*)(smem + OFF_IN(nxt)))[tid];
                bulk_g2s(sb + OFF_A(nxt) + tid * A_STRIDE_B, g_featsH + ii * C_IN, 128, MBAR(cur));
            }
            if (tid == 0)
                bulk_g2s(sb + OFF_OUT(nxt), (const char*)out_map + MAPB(k1, m1),
                         rows1 * idxsz, MBAR(cur));
        }
        if (rows2 && tid == 1)
            bulk_g2s(sb + OFF_IN(cur), (const char*)in_map + MAPB(k2, m2),
                     rows2 * idxsz, MBAR(cur));

        // ---- MMA: 16 rows x 32 cols x 64 k per warp = 4 ldmatrix.x4 + 16 HMMA ----
        float acc[4][4];
#pragma unroll
        for (int nt = 0; nt < 4; ++nt)
#pragma unroll
            for (int i = 0; i < 4; ++i) acc[nt][i] = 0.f;

        const uint32_t abase = sb + OFF_A(cur) + a_lane_off;
#pragma unroll
        for (int kc = 0; kc < 4; ++kc) {
            uint32_t a0, a1, a2, a3;
            ldm_x4(a0, a1, a2, a3, abase + kc * 32);
#pragma unroll
            for (int nt = 0; nt < 4; ++nt)
                mma_f16(acc[nt][0], acc[nt][1], acc[nt][2], acc[nt][3],
                        a0, a1, a2, a3, B[kc][nt][0], B[kc][nt][1]);
        }

        // ---- scatter epilogue: shuffle-assembled v2.f16x2 reductions ----
        // Lane pair (tig, tig^1) holds 4 consecutive cols of rows r0/r1 split 2+2.
        // Pack the "other row" pair, one bfly exchange per nt: even lanes emit
        // row r0's 4-col vector, odd lanes row r1's. 4 red instr/lane (was 8).
        {
            const char* osm = smem + OFF_OUT(cur);
            const int r0 = wbase + grp;
            const int odd = tig & 1;
            const int myrow = odd ? r0 + 8 : r0;
            const bool valid = myrow < rows;
            uint32_t oi = 0;
            if (valid) oi = is64 ? (uint32_t)((const long long*)osm)[myrow]
                                 : (uint32_t)((const int*)osm)[myrow];
            __half* pbase = outH + oi * (uint32_t)C_OUT + ((tig & 2) << 1);
#pragma unroll
            for (int nt = 0; nt < 4; ++nt) {
                uint32_t own_r0 = h2u(__floats2half2_rn(acc[nt][0], acc[nt][1]));
                uint32_t own_r1 = h2u(__floats2half2_rn(acc[nt][2], acc[nt][3]));
                uint32_t sent = odd ? own_r0 : own_r1;     // send the other row's pair
                uint32_t recv = __shfl_xor_sync(0xffffffffu, sent, 1);
                uint32_t v0 = odd ? recv : own_r0;         // low 2 cols
                uint32_t v1 = odd ? own_r1 : recv;         // high 2 cols
                if (valid) red_h2v2(pbase + 8 * nt, v0, v1);
            }
        }

        // advance to t+1
        pk = k1; pm = m1;
    }
#undef MBAR
#undef ADV
#undef ROWS_AT
#undef MAPB
}

extern "C" void kernel_launch(void* const* d_in, const int* in_sizes, int n_in,
                              void* d_out, int out_size) {
    const float* feats  = (const float*)d_in[0];
    const float* weight = (const float*)d_in[1];
    const void*  in_map  = d_in[2];
    const void*  out_map = d_in[3];

    int K = in_sizes[1] / (C_IN * C_OUT);           // 27
    int M = in_sizes[2] / K;                        // 100000
    int tilesPerK = (M + M_TILE - 1) / M_TILE;      // 782
    int nTiles = K * tilesPerK;                     // 21114
    int chunk = (nTiles + GRID - 1) / GRID;         // 36

    static int attr_done = 0;
    if (!attr_done) {
        cudaFuncSetAttribute(spconv_mma,
                             cudaFuncAttributeMaxDynamicSharedMemorySize, SMEM_TOTAL);
        attr_done = 1;
    }

    prep_kernel<<<2368, 256>>>((const float4*)feats, in_sizes[0] / 4,
                               out_size / 8,          // fp16 accum as uint4 count
                               (const long long*)in_map);
    spconv_mma<<<GRID, THREADS, SMEM_TOTAL>>>(weight, in_map, out_map,
                                              M, tilesPerK, nTiles, chunk);
    convert_out<<<2368, 256>>>((float4*)d_out, out_size / 4);
}